// round 1
// baseline (speedup 1.0000x reference)
#include <cuda_runtime.h>
#include <stdint.h>

// Instant-NGP multiresolution hash-grid encode.
// x: [N,3] fp32, tables: [16, 2^19, 2] fp32 -> out: [N, 32] fp32.
//
// Thread mapping: global thread t -> point = t>>4, level = t&15.
//  - warp = 2 points x 16 levels; output float2 stores are 256B contiguous.
//  - x loads broadcast across the 16 threads of a point.

#define NGP_LEVELS 16
#define NGP_T      524288u          // 2^19
#define NGP_TMASK  (NGP_T - 1u)
#define NGP_P1     2654435761u
#define NGP_P2     805459861u

__constant__ float c_res[NGP_LEVELS] = {
    16.f, 24.f, 36.f, 54.f, 81.f, 121.f, 182.f, 273.f,
    410.f, 615.f, 922.f, 1383.f, 2075.f, 3113.f, 4670.f, 7006.f
};

__global__ __launch_bounds__(256)
void ngp_encode_kernel(const float* __restrict__ x,
                       const float* __restrict__ tables,
                       float* __restrict__ out,
                       int npts)
{
    int t = blockIdx.x * blockDim.x + threadIdx.x;
    int point = t >> 4;
    int level = t & 15;
    if (point >= npts) return;

    // ---- load point coords (broadcast across the 16 level-threads) ----
    const float* xp = x + (size_t)point * 3;
    float px = __ldg(xp + 0);
    float py = __ldg(xp + 1);
    float pz = __ldg(xp + 2);

    float res = c_res[level];

    // ---- grid coords + trilinear fracs (bit-matches jnp: fp32 mul/floor/sub) ----
    float sx = px * res, sy = py * res, sz = pz * res;
    float fx_ = floorf(sx), fy_ = floorf(sy), fz_ = floorf(sz);
    float gx = sx - fx_, gy = sy - fy_, gz = sz - fz_;
    uint32_t ix = (uint32_t)fx_, iy = (uint32_t)fy_, iz = (uint32_t)fz_;

    // ---- incremental spatial hash terms ----
    uint32_t hx0 = ix;             // prime = 1
    uint32_t hx1 = ix + 1u;
    uint32_t hy0 = iy * NGP_P1;
    uint32_t hy1 = hy0 + NGP_P1;   // (iy+1)*P1 via uint wrap
    uint32_t hz0 = iz * NGP_P2;
    uint32_t hz1 = hz0 + NGP_P2;

    // 8 corner indices (corner c: i = c>>2, j = (c>>1)&1, k = c&1)
    uint32_t idx0 = (hx0 ^ hy0 ^ hz0) & NGP_TMASK;
    uint32_t idx1 = (hx0 ^ hy0 ^ hz1) & NGP_TMASK;
    uint32_t idx2 = (hx0 ^ hy1 ^ hz0) & NGP_TMASK;
    uint32_t idx3 = (hx0 ^ hy1 ^ hz1) & NGP_TMASK;
    uint32_t idx4 = (hx1 ^ hy0 ^ hz0) & NGP_TMASK;
    uint32_t idx5 = (hx1 ^ hy0 ^ hz1) & NGP_TMASK;
    uint32_t idx6 = (hx1 ^ hy1 ^ hz0) & NGP_TMASK;
    uint32_t idx7 = (hx1 ^ hy1 ^ hz1) & NGP_TMASK;

    const float2* tbl = (const float2*)(tables) + (size_t)level * NGP_T;

    // issue all 8 gathers up front (MLP=8)
    float2 t0 = __ldg(tbl + idx0);
    float2 t1 = __ldg(tbl + idx1);
    float2 t2 = __ldg(tbl + idx2);
    float2 t3 = __ldg(tbl + idx3);
    float2 t4 = __ldg(tbl + idx4);
    float2 t5 = __ldg(tbl + idx5);
    float2 t6 = __ldg(tbl + idx6);
    float2 t7 = __ldg(tbl + idx7);

    // ---- trilinear weights ----
    float wx0 = 1.f - gx, wx1 = gx;
    float wy0 = 1.f - gy, wy1 = gy;
    float wz0 = 1.f - gz, wz1 = gz;

    float w0 = wx0 * wy0 * wz0;
    float w1 = wx0 * wy0 * wz1;
    float w2 = wx0 * wy1 * wz0;
    float w3 = wx0 * wy1 * wz1;
    float w4 = wx1 * wy0 * wz0;
    float w5 = wx1 * wy0 * wz1;
    float w6 = wx1 * wy1 * wz0;
    float w7 = wx1 * wy1 * wz1;

    float ax = 0.f, ay = 0.f;
    ax = fmaf(w0, t0.x, ax);  ay = fmaf(w0, t0.y, ay);
    ax = fmaf(w1, t1.x, ax);  ay = fmaf(w1, t1.y, ay);
    ax = fmaf(w2, t2.x, ax);  ay = fmaf(w2, t2.y, ay);
    ax = fmaf(w3, t3.x, ax);  ay = fmaf(w3, t3.y, ay);
    ax = fmaf(w4, t4.x, ax);  ay = fmaf(w4, t4.y, ay);
    ax = fmaf(w5, t5.x, ax);  ay = fmaf(w5, t5.y, ay);
    ax = fmaf(w6, t6.x, ax);  ay = fmaf(w6, t6.y, ay);
    ax = fmaf(w7, t7.x, ax);  ay = fmaf(w7, t7.y, ay);

    // out[point, level*2 .. level*2+1] — warp writes 2x128B contiguous
    float2* op = (float2*)out + (size_t)point * NGP_LEVELS + level;
    *op = make_float2(ax, ay);
}

extern "C" void kernel_launch(void* const* d_in, const int* in_sizes, int n_in,
                              void* d_out, int out_size)
{
    const float* x      = (const float*)d_in[0];   // [N,3]
    const float* tables = (const float*)d_in[1];   // [16, 2^19, 2]
    float* out          = (float*)d_out;           // [N,32]

    int npts = in_sizes[0] / 3;
    int total_threads = npts * NGP_LEVELS;
    int block = 256;
    int grid = (total_threads + block - 1) / block;

    ngp_encode_kernel<<<grid, block>>>(x, tables, out, npts);
}

// round 4
// speedup vs baseline: 1.2343x; 1.2343x over previous
#include <cuda_runtime.h>
#include <stdint.h>

// Instant-NGP multiresolution hash-grid encode.
// x: [N,3] fp32, tables: [16, 2^19, 2] fp32 -> out: [N, 32] fp32.
//
// Thread mapping: global thread t -> point = t>>4, level = t&15.
// Key optimization: x-dim hash prime is 1, so for even ix the corners
// (ix,j,k) and (ix+1,j,k) land at table indices idx and idx^1 — one
// aligned float4. 4x LDG.128 replaces 8x LDG.64 (halves L1 wavefronts
// for even-ix lanes; ~0.75x total).

#define NGP_LEVELS 16
#define NGP_T      524288u          // 2^19
#define NGP_TMASK  (NGP_T - 1u)
#define NGP_P1     2654435761u
#define NGP_P2     805459861u

__constant__ float c_res[NGP_LEVELS] = {
    16.f, 24.f, 36.f, 54.f, 81.f, 121.f, 182.f, 273.f,
    410.f, 615.f, 922.f, 1383.f, 2075.f, 3113.f, 4670.f, 7006.f
};

__global__ __launch_bounds__(256)
void ngp_encode_kernel(const float* __restrict__ x,
                       const float* __restrict__ tables,
                       float* __restrict__ out,
                       int npts)
{
    int t = blockIdx.x * blockDim.x + threadIdx.x;
    int point = t >> 4;
    int level = t & 15;
    if (point >= npts) return;

    // ---- point coords (broadcast across the 16 level-threads) ----
    const float* xp = x + (size_t)point * 3;
    float px = __ldg(xp + 0);
    float py = __ldg(xp + 1);
    float pz = __ldg(xp + 2);

    float res = c_res[level];

    // ---- grid coords + trilinear fracs (bit-matches jnp fp32 path) ----
    float sx = px * res, sy = py * res, sz = pz * res;
    float fx_ = floorf(sx), fy_ = floorf(sy), fz_ = floorf(sz);
    float gx = sx - fx_, gy = sy - fy_, gz = sz - fz_;
    uint32_t ix = (uint32_t)fx_, iy = (uint32_t)fy_, iz = (uint32_t)fz_;

    // ---- incremental hash terms ----
    uint32_t hy0 = iy * NGP_P1;
    uint32_t hy1 = hy0 + NGP_P1;
    uint32_t hz0 = iz * NGP_P2;
    uint32_t hz1 = hz0 + NGP_P2;

    uint32_t m00 = hy0 ^ hz0;
    uint32_t m01 = hy0 ^ hz1;
    uint32_t m10 = hy1 ^ hz0;
    uint32_t m11 = hy1 ^ hz1;

    const float2* tbl = (const float2*)(tables) + (size_t)level * NGP_T;

    // corners: fA_jk = (x=ix, j, k), fB_jk = (x=ix+1, j, k)
    float2 fA00, fA01, fA10, fA11, fB00, fB01, fB10, fB11;

    if ((ix & 1u) == 0u) {
        // even ix: (ix+1) = ix^1 -> corner pair = aligned float4
        uint32_t a00 = (ix ^ m00) & NGP_TMASK;
        uint32_t a01 = (ix ^ m01) & NGP_TMASK;
        uint32_t a10 = (ix ^ m10) & NGP_TMASK;
        uint32_t a11 = (ix ^ m11) & NGP_TMASK;

        const float4* t4 = (const float4*)tbl;
        float4 q00 = __ldg(t4 + (a00 >> 1));
        float4 q01 = __ldg(t4 + (a01 >> 1));
        float4 q10 = __ldg(t4 + (a10 >> 1));
        float4 q11 = __ldg(t4 + (a11 >> 1));

        bool s00 = (a00 & 1u);
        bool s01 = (a01 & 1u);
        bool s10 = (a10 & 1u);
        bool s11 = (a11 & 1u);

        fA00 = s00 ? make_float2(q00.z, q00.w) : make_float2(q00.x, q00.y);
        fB00 = s00 ? make_float2(q00.x, q00.y) : make_float2(q00.z, q00.w);
        fA01 = s01 ? make_float2(q01.z, q01.w) : make_float2(q01.x, q01.y);
        fB01 = s01 ? make_float2(q01.x, q01.y) : make_float2(q01.z, q01.w);
        fA10 = s10 ? make_float2(q10.z, q10.w) : make_float2(q10.x, q10.y);
        fB10 = s10 ? make_float2(q10.x, q10.y) : make_float2(q10.z, q10.w);
        fA11 = s11 ? make_float2(q11.z, q11.w) : make_float2(q11.x, q11.y);
        fB11 = s11 ? make_float2(q11.x, q11.y) : make_float2(q11.z, q11.w);
    } else {
        // odd ix: carry breaks the XOR identity -> 8 scalar gathers
        uint32_t ix1 = ix + 1u;
        uint32_t a0 = (ix  ^ m00) & NGP_TMASK;
        uint32_t a1 = (ix  ^ m01) & NGP_TMASK;
        uint32_t a2 = (ix  ^ m10) & NGP_TMASK;
        uint32_t a3 = (ix  ^ m11) & NGP_TMASK;
        uint32_t a4 = (ix1 ^ m00) & NGP_TMASK;
        uint32_t a5 = (ix1 ^ m01) & NGP_TMASK;
        uint32_t a6 = (ix1 ^ m10) & NGP_TMASK;
        uint32_t a7 = (ix1 ^ m11) & NGP_TMASK;

        fA00 = __ldg(tbl + a0);
        fA01 = __ldg(tbl + a1);
        fA10 = __ldg(tbl + a2);
        fA11 = __ldg(tbl + a3);
        fB00 = __ldg(tbl + a4);
        fB01 = __ldg(tbl + a5);
        fB10 = __ldg(tbl + a6);
        fB11 = __ldg(tbl + a7);
    }

    // ---- trilinear weights ----
    float wx0 = 1.f - gx, wx1 = gx;
    float wy0 = 1.f - gy, wy1 = gy;
    float wz0 = 1.f - gz, wz1 = gz;

    float w00 = wy0 * wz0;
    float w01 = wy0 * wz1;
    float w10 = wy1 * wz0;
    float w11 = wy1 * wz1;

    // accumulate x=ix plane and x=ix+1 plane, then combine with wx
    float axA = 0.f, ayA = 0.f, axB = 0.f, ayB = 0.f;
    axA = fmaf(w00, fA00.x, axA);  ayA = fmaf(w00, fA00.y, ayA);
    axA = fmaf(w01, fA01.x, axA);  ayA = fmaf(w01, fA01.y, ayA);
    axA = fmaf(w10, fA10.x, axA);  ayA = fmaf(w10, fA10.y, ayA);
    axA = fmaf(w11, fA11.x, axA);  ayA = fmaf(w11, fA11.y, ayA);
    axB = fmaf(w00, fB00.x, axB);  ayB = fmaf(w00, fB00.y, ayB);
    axB = fmaf(w01, fB01.x, axB);  ayB = fmaf(w01, fB01.y, ayB);
    axB = fmaf(w10, fB10.x, axB);  ayB = fmaf(w10, fB10.y, ayB);
    axB = fmaf(w11, fB11.x, axB);  ayB = fmaf(w11, fB11.y, ayB);

    float ax = wx0 * axA + wx1 * axB;
    float ay = wx0 * ayA + wx1 * ayB;

    // out[point, level*2 .. level*2+1] — warp writes 256B contiguous
    float2* op = (float2*)out + (size_t)point * NGP_LEVELS + level;
    *op = make_float2(ax, ay);
}

extern "C" void kernel_launch(void* const* d_in, const int* in_sizes, int n_in,
                              void* d_out, int out_size)
{
    const float* x      = (const float*)d_in[0];   // [N,3]
    const float* tables = (const float*)d_in[1];   // [16, 2^19, 2]
    float* out          = (float*)d_out;           // [N,32]

    int npts = in_sizes[0] / 3;
    int total_threads = npts * NGP_LEVELS;
    int block = 256;
    int grid = (total_threads + block - 1) / block;

    ngp_encode_kernel<<<grid, block>>>(x, tables, out, npts);
}